// round 5
// baseline (speedup 1.0000x reference)
#include <cuda_runtime.h>
#include <cstdint>

// ---------------------------------------------------------------------------
// P2G quadratic B-spline, 64^3 grid, B<=8 batches — GATHER formulation.
//
// Round-3 strategy: eliminate the 18M REDG atomic lanes (the measured binder,
// 1.29 cyc/lane) entirely:
//   1. counting-sort particles by cell id (B*64^3 = 2M bins, CSR offsets)
//   2. one thread per 4 z-cells gathers from 9 neighbor (x,y) rows; the 3
//      z-neighbor bins per row are CONTIGUOUS in sorted order -> 1 range/row
//   3. weight taps per (ox,oy) row are compile-time constants (unrolled);
//      z-tap routed to 4 register accumulator slots via selects
//   4. final divide fused into the gather (no scratch grid at all)
// ---------------------------------------------------------------------------

#define GRID_N    64
#define GRID_N3   (GRID_N * GRID_N * GRID_N)     // 262144
#define B_MAX     8
#define NBINS_MAX (B_MAX * GRID_N3)              // 2,097,152
#define REC_CAP   (2 * 1024 * 1024)              // max particles supported

#define SCAN_BINS_PER_BLOCK 2048
#define SCAN_T              256
#define SCAN_PER            8                    // bins per thread

__device__ int    g_cnt[NBINS_MAX];
__device__ int    g_off[NBINS_MAX + 1];
__device__ int    g_cur[NBINS_MAX];
__device__ int    g_bsum[1024];
__device__ float4 g_rec[REC_CAP];                // (fx, fy, Xz, prob)

// ---------------------------------------------------------------------------
// K0: zero the bin counters

__global__ void k0_zero(int n4) {
    int4* p = reinterpret_cast<int4*>(g_cnt);
    for (int i = blockIdx.x * blockDim.x + threadIdx.x; i < n4;
         i += gridDim.x * blockDim.x)
        p[i] = make_int4(0, 0, 0, 0);
}

// ---------------------------------------------------------------------------
// key helper (must be bit-identical between K1 and K3)

__device__ __forceinline__ int particle_key(const float* __restrict__ pos,
                                            const int* __restrict__ bidx,
                                            int i,
                                            float& Xx, float& Xy, float& Xz,
                                            int& bx, int& by, int& bz) {
    const float LO = 1e-5f, HI = 1.0f - 1e-5f;
    float px = fminf(fmaxf(pos[3 * i + 0], LO), HI);
    float py = fminf(fmaxf(pos[3 * i + 1], LO), HI);
    float pz = fminf(fmaxf(pos[3 * i + 2], LO), HI);
    Xx = px * 64.0f; Xy = py * 64.0f; Xz = pz * 64.0f;
    bx = (int)Xx; by = (int)Xy; bz = (int)Xz;     // in [0,63] after clip
    return (((bidx[i] << 6) | bx) << 6 | by) << 6 | bz;
}

// ---------------------------------------------------------------------------
// K1: histogram

__global__ void __launch_bounds__(256)
k1_hist(const float* __restrict__ pos, const int* __restrict__ bidx, int L) {
    int i = blockIdx.x * blockDim.x + threadIdx.x;
    if (i >= L) return;
    float Xx, Xy, Xz; int bx, by, bz;
    int key = particle_key(pos, bidx, i, Xx, Xy, Xz, bx, by, bz);
    atomicAdd(&g_cnt[key], 1);                    // result unused -> RED
}

// ---------------------------------------------------------------------------
// K2a: per-block partial sums (2048 bins / block)

__global__ void k2a_partial(int nbins) {
    __shared__ int sm[SCAN_T];
    int b = blockIdx.x, t = threadIdx.x;
    int base = b * SCAN_BINS_PER_BLOCK + t * SCAN_PER;
    int s = 0;
    #pragma unroll
    for (int k = 0; k < SCAN_PER; k++) s += g_cnt[base + k];
    sm[t] = s;
    __syncthreads();
    for (int d = SCAN_T / 2; d > 0; d >>= 1) {
        if (t < d) sm[t] += sm[t + d];
        __syncthreads();
    }
    if (t == 0) g_bsum[b] = sm[0];
}

// K2b: exclusive scan of block sums (nb <= 1024), also writes g_off[nbins]

__global__ void k2b_scan(int nb, int nbins) {
    __shared__ int sm[1024];
    int t = threadIdx.x;
    int v = (t < nb) ? g_bsum[t] : 0;
    sm[t] = v;
    __syncthreads();
    for (int d = 1; d < 1024; d <<= 1) {
        int a = (t >= d) ? sm[t - d] : 0;
        __syncthreads();
        sm[t] += a;
        __syncthreads();
    }
    if (t < nb) g_bsum[t] = sm[t] - v;            // exclusive block base
    if (t == nb - 1) g_off[nbins] = sm[t];        // total = L
}

// K2c: per-bin exclusive offsets; also initialize g_cur

__global__ void k2c_offsets(int nbins) {
    __shared__ int sm[SCAN_T];
    int b = blockIdx.x, t = threadIdx.x;
    int base = b * SCAN_BINS_PER_BLOCK + t * SCAN_PER;
    int c[SCAN_PER], pre[SCAN_PER];
    int s = 0;
    #pragma unroll
    for (int k = 0; k < SCAN_PER; k++) {
        c[k] = g_cnt[base + k];
        pre[k] = s;
        s += c[k];
    }
    sm[t] = s;
    __syncthreads();
    for (int d = 1; d < SCAN_T; d <<= 1) {
        int a = (t >= d) ? sm[t - d] : 0;
        __syncthreads();
        sm[t] += a;
        __syncthreads();
    }
    int o = g_bsum[b] + (sm[t] - s);
    #pragma unroll
    for (int k = 0; k < SCAN_PER; k++) {
        int v = o + pre[k];
        g_off[base + k] = v;
        g_cur[base + k] = v;
    }
}

// ---------------------------------------------------------------------------
// K3: reorder particles into sorted record array

__global__ void __launch_bounds__(256)
k3_reorder(const float* __restrict__ pos, const float* __restrict__ prob,
           const int* __restrict__ bidx, int L) {
    int i = blockIdx.x * blockDim.x + threadIdx.x;
    if (i >= L) return;
    float Xx, Xy, Xz; int bx, by, bz;
    int key = particle_key(pos, bidx, i, Xx, Xy, Xz, bx, by, bz);
    float fx = Xx - (float)bx;
    float fy = Xy - (float)by;
    int r = atomicAdd(&g_cur[key], 1);
    g_rec[r] = make_float4(fx, fy, Xz, prob[i]);
}

// ---------------------------------------------------------------------------
// K4: gather + divide.  One thread per 4 z-cells.

__global__ void __launch_bounds__(256)
k4_gather(float* __restrict__ out, int total_threads) {
    int t = blockIdx.x * blockDim.x + threadIdx.x;
    if (t >= total_threads) return;

    int row = t >> 4;                 // (b,x,y) row id = ((b*64+x)*64+y)
    int zq  = (t & 15) << 2;          // first owned z-cell (0,4,...,60)
    int y = row & 63;
    int x = (row >> 6) & 63;

    float aw[4] = {0.f, 0.f, 0.f, 0.f};
    float ap[4] = {0.f, 0.f, 0.f, 0.f};

    int blo = max(zq - 1, 0);
    int bhi = min(zq + 4, 63);

    #pragma unroll
    for (int ox = -1; ox <= 1; ox++) {
        int nx = x + ox;
        if ((unsigned)nx >= (unsigned)GRID_N) continue;
        #pragma unroll
        for (int oy = -1; oy <= 1; oy++) {
            int ny = y + oy;
            if ((unsigned)ny >= (unsigned)GRID_N) continue;
            int cb = (row + ox * 64 + oy) << 6;     // neighbor row * 64
            int s = g_off[cb + blo];
            int e = g_off[cb + bhi + 1];
            const int TX = 1 - ox;                   // compile-time after unroll
            const int TY = 1 - oy;
            for (int j = s; j < e; j++) {
                float4 r = g_rec[j];
                float wxp = (TX == 0) ? 0.5f * (1.f - r.x) * (1.f - r.x)
                          : (TX == 1) ? 0.75f - (r.x - 0.5f) * (r.x - 0.5f)
                                      : 0.5f * r.x * r.x;
                float wyp = (TY == 0) ? 0.5f * (1.f - r.y) * (1.f - r.y)
                          : (TY == 1) ? 0.75f - (r.y - 0.5f) * (r.y - 0.5f)
                                      : 0.5f * r.y * r.y;
                int   bz = (int)r.z;
                float fz = r.z - (float)bz;
                float c  = wxp * wyp;
                float a0 = c * 0.5f * (1.f - fz) * (1.f - fz);
                float a1 = c * (0.75f - (fz - 0.5f) * (fz - 0.5f));
                float a2 = c * 0.5f * fz * fz;
                int   tt = bz - zq;
                #pragma unroll
                for (int s4 = 0; s4 < 4; s4++) {
                    float ws = (tt == s4 + 1) ? a0
                             : (tt == s4)     ? a1
                             : (tt == s4 - 1) ? a2 : 0.f;
                    aw[s4] += ws;
                    ap[s4]  = fmaf(ws, r.w, ap[s4]);
                }
            }
        }
    }

    float4 o;
    o.x = ap[0] / (aw[0] + 1e-7f);
    o.y = ap[1] / (aw[1] + 1e-7f);
    o.z = ap[2] / (aw[2] + 1e-7f);
    o.w = ap[3] / (aw[3] + 1e-7f);
    *reinterpret_cast<float4*>(out + (row << 6) + zq) = o;
}

// ---------------------------------------------------------------------------

extern "C" void kernel_launch(void* const* d_in, const int* in_sizes, int n_in,
                              void* d_out, int out_size) {
    const float* pos  = (const float*)d_in[0];
    const float* prob = (const float*)d_in[1];
    const int*   bidx = (const int*)d_in[2];
    float*       out  = (float*)d_out;

    int L     = in_sizes[1];                 // particle count
    int B     = out_size / GRID_N3;          // batches
    int nbins = B * GRID_N3;
    int nb    = nbins / SCAN_BINS_PER_BLOCK; // <= 1024

    k0_zero<<<592, 256>>>(nbins / 4);
    k1_hist<<<(L + 255) / 256, 256>>>(pos, bidx, L);
    k2a_partial<<<nb, SCAN_T>>>(nbins);
    k2b_scan<<<1, 1024>>>(nb, nbins);
    k2c_offsets<<<nb, SCAN_T>>>(nbins);
    k3_reorder<<<(L + 255) / 256, 256>>>(pos, prob, bidx, L);

    int gthreads = (B * GRID_N * GRID_N) * 16;   // 16 threads per row
    k4_gather<<<(gthreads + 255) / 256, 256>>>(out, gthreads);
}